// round 4
// baseline (speedup 1.0000x reference)
#include <cuda_runtime.h>
#include <cstdint>

#define C_DIM 256
#define K_DIM 1024
#define HW    1024
#define TM    128
#define TN    128
#define CK    64
#define NTHREADS 256

// ---------------- device globals (scratch; no runtime allocation) ----------------
__device__ __align__(16) float  g_embT[C_DIM * K_DIM];  // emb transposed: [c][k]
__device__ __align__(16) float  g_esq[K_DIM];           // ||e_k||^2 (fp32, sequential order)
__device__ __align__(16) float  g_zsq[64 * HW];         // ||z_n||^2 (fp32, sequential order)
__device__ double g_sumsq;
__device__ double g_sumlin;

// ---------------- tiny helper kernels ----------------
__global__ void vq_zero_kernel() {
    g_sumsq = 0.0;
    g_sumlin = 0.0;
}

// emb [K][C] -> g_embT [C][K], classic 32x32 smem transpose
__global__ void vq_transpose_kernel(const float* __restrict__ emb) {
    __shared__ float t[32][33];
    int k0 = blockIdx.x * 32, c0 = blockIdx.y * 32;
    int tx = threadIdx.x, ty = threadIdx.y;
#pragma unroll
    for (int r = ty; r < 32; r += 8)
        t[r][tx] = emb[(size_t)(k0 + r) * C_DIM + c0 + tx];
    __syncthreads();
#pragma unroll
    for (int r = ty; r < 32; r += 8)
        g_embT[(size_t)(c0 + r) * K_DIM + k0 + tx] = t[tx][r];
}

// ||e_k||^2: one thread per code, STRICT sequential fp32, mul/add separately rounded
// (emulates XLA CPU reduce ordering)
__global__ void vq_esq_kernel(const float* __restrict__ emb) {
    int k = blockIdx.x * blockDim.x + threadIdx.x;
    if (k >= K_DIM) return;
    const float* row = emb + (size_t)k * C_DIM;
    float acc = 0.0f;
    for (int c = 0; c < C_DIM; c++) {
        float v = row[c];
        acc = __fadd_rn(acc, __fmul_rn(v, v));
    }
    g_esq[k] = acc;
}

// ||z_n||^2: one thread per token (b,s), STRICT sequential fp32 over c ascending,
// mul/add separately rounded. Loads coalesced across s.
__global__ void vq_zsq_kernel(const float* __restrict__ z) {
    int n = blockIdx.x * blockDim.x + threadIdx.x;   // 0..65535
    int b = n >> 10, s = n & (HW - 1);
    const float* base = z + ((size_t)b * C_DIM) * HW + s;
    float acc = 0.0f;
    for (int c = 0; c < C_DIM; c++) {
        float v = base[(size_t)c * HW];
        acc = __fadd_rn(acc, __fmul_rn(v, v));
    }
    g_zsq[n] = acc;
}

// ---------------- packed f32x2 helpers ----------------
__device__ __forceinline__ unsigned long long splat2(float x) {
    unsigned long long r;
    unsigned int xi = __float_as_uint(x);
    asm("mov.b64 %0, {%1, %1};" : "=l"(r) : "r"(xi));
    return r;
}
__device__ __forceinline__ void fma2(unsigned long long& d,
                                     unsigned long long a,
                                     unsigned long long b) {
    asm("fma.rn.f32x2 %0, %1, %2, %0;" : "+l"(d) : "l"(a), "l"(b));
}
__device__ __forceinline__ void unpack2(unsigned long long v, float& lo, float& hi) {
    unsigned int l, h;
    asm("mov.b64 {%0, %1}, %2;" : "=r"(l), "=r"(h) : "l"(v));
    lo = __uint_as_float(l);
    hi = __uint_as_float(h);
}

// Emulate reference fp32 chain: d = fl( fl(zsq + esq) - fl(2*ez) )
__device__ __forceinline__ float ref_dist(float zsq, float esq, float ez) {
    float t = __fadd_rn(zsq, esq);
    return __fadd_rn(t, __fmul_rn(-2.0f, ez));
}

// ---------------- main kernel: distances + argmin + gather + loss ----------------
__global__ __launch_bounds__(NTHREADS, 1)
void vq_main_kernel(const float* __restrict__ z, const float* __restrict__ emb,
                    float* __restrict__ out) {
    extern __shared__ float smem[];
    float* z_tile = smem;                       // [256][128]  (c-major, token contiguous)
    float* e_tile = smem + C_DIM * TM;          // [64][128]   (c-major, code contiguous)
    int*   s_inds = (int*)(e_tile + CK * TN);   // [128]
    float* s_red  = (float*)(s_inds + TM);      // [16]

    const int tid = threadIdx.x;
    const int tx = tid & 15;   // code group
    const int ty = tid >> 4;   // token group
    const int blk = blockIdx.x;
    const int b  = blk >> 3;               // 8 blocks per image (1024/128)
    const int s0 = (blk & 7) * TM;
    const float* zb = z + ((size_t)b * C_DIM) * HW + s0;

    // load z tile: z_tile[c][i] = z[b][c][s0+i]  (fully coalesced)
#pragma unroll
    for (int r = 0; r < 32; r++) {
        int idx = tid + r * NTHREADS;          // 0..8191 float4s
        int c = idx >> 5, i4 = idx & 31;
        *(float4*)&z_tile[c * TM + i4 * 4] =
            *(const float4*)(zb + (size_t)c * HW + i4 * 4);
    }

    // per-token ||z||^2 (reference fp32 bits) for the 8 tokens this thread owns
    float zs8[8];
#pragma unroll
    for (int t = 0; t < 8; t++)
        zs8[t] = g_zsq[b * HW + s0 + (ty << 3) + t];

    float bmin[8];
    int   bidx[8];
#pragma unroll
    for (int t = 0; t < 8; t++) { bmin[t] = 3.4e38f; bidx[t] = 0; }

    for (int kc = 0; kc < 8; kc++) {           // 8 code chunks of 128
        unsigned long long acc[8][4];
#pragma unroll
        for (int t = 0; t < 8; t++)
#pragma unroll
            for (int p = 0; p < 4; p++) acc[t][p] = 0ull;

        for (int cc = 0; cc < 4; cc++) {       // C staged in 4 chunks of 64, k ASCENDING
            __syncthreads();
            {   // stage embT[cc*64 .. +64][kc*128 .. +128] into smem (coalesced, conflict-free)
                const float* src = g_embT + (size_t)(cc * CK) * K_DIM + kc * TN;
#pragma unroll
                for (int r = 0; r < 8; r++) {
                    int idx = tid + r * NTHREADS;  // 0..2047 float4s
                    int c = idx >> 5, k4 = idx & 31;
                    *(float4*)&e_tile[c * TN + k4 * 4] =
                        *(const float4*)(src + (size_t)c * K_DIM + k4 * 4);
                }
            }
            __syncthreads();

            const float* zr = z_tile + (cc * CK) * TM + (ty << 3);
            const float* er = e_tile + (tx << 2);
#pragma unroll 8
            for (int cl = 0; cl < CK; cl++) {
                float4 zA = *(const float4*)(zr);
                float4 zB = *(const float4*)(zr + 4);
                ulonglong2 eA = *(const ulonglong2*)(er);        // codes tx*4 .. +3
                ulonglong2 eB = *(const ulonglong2*)(er + 64);   // codes 64+tx*4 .. +3
                float zv[8] = {zA.x, zA.y, zA.z, zA.w, zB.x, zB.y, zB.z, zB.w};
                unsigned long long e0 = eA.x, e1 = eA.y, e2 = eB.x, e3 = eB.y;
#pragma unroll
                for (int t = 0; t < 8; t++) {
                    unsigned long long zs = splat2(zv[t]);
                    fma2(acc[t][0], zs, e0);   // sequential fused-FMA over c, per code
                    fma2(acc[t][1], zs, e1);
                    fma2(acc[t][2], zs, e2);
                    fma2(acc[t][3], zs, e3);
                }
                zr += TM;
                er += TN;
            }
        }

        // epilogue: reference-emulated dist = fl(fl(zsq+esq) - fl(2*ez))
        const int kA = kc * TN + (tx << 2);
        const int kB = kA + 64;
        float4 eqA = *(const float4*)&g_esq[kA];
        float4 eqB = *(const float4*)&g_esq[kB];
#pragma unroll
        for (int t = 0; t < 8; t++) {
            const float zs = zs8[t];
            float lo, hi;
            unpack2(acc[t][0], lo, hi);
            float da0 = ref_dist(zs, eqA.x, lo);
            float da1 = ref_dist(zs, eqA.y, hi);
            unpack2(acc[t][1], lo, hi);
            float da2 = ref_dist(zs, eqA.z, lo);
            float da3 = ref_dist(zs, eqA.w, hi);
            unpack2(acc[t][2], lo, hi);
            float db0 = ref_dist(zs, eqB.x, lo);
            float db1 = ref_dist(zs, eqB.y, hi);
            unpack2(acc[t][3], lo, hi);
            float db2 = ref_dist(zs, eqB.z, lo);
            float db3 = ref_dist(zs, eqB.w, hi);

            float bd = da0; int bk = kA;                    // ascending k, strict <
            if (da1 < bd) { bd = da1; bk = kA + 1; }
            if (da2 < bd) { bd = da2; bk = kA + 2; }
            if (da3 < bd) { bd = da3; bk = kA + 3; }
            if (db0 < bd) { bd = db0; bk = kB;     }
            if (db1 < bd) { bd = db1; bk = kB + 1; }
            if (db2 < bd) { bd = db2; bk = kB + 2; }
            if (db3 < bd) { bd = db3; bk = kB + 3; }
#pragma unroll
            for (int m = 8; m > 0; m >>= 1) {               // reduce over 16 tx lanes
                float od = __shfl_xor_sync(0xffffffffu, bd, m);
                int   ok = __shfl_xor_sync(0xffffffffu, bk, m);
                if (od < bd || (od == bd && ok < bk)) { bd = od; bk = ok; }
            }
            if (bd < bmin[t]) { bmin[t] = bd; bidx[t] = bk; }  // earlier chunk wins ties
        }
    }

    if (tx == 0) {
#pragma unroll
        for (int t = 0; t < 8; t++) s_inds[(ty << 3) + t] = bidx[t];
    }
    __syncthreads();

    // gather z_q = emb[ind], write NCHW (coalesced), accumulate loss terms
    const int i  = tid & 127;
    const int cg = tid >> 7;                    // 0/1: even/odd c rows
    const int ind = s_inds[i];
    const float* erow = emb + (size_t)ind * C_DIM;
    float lsq = 0.0f, llin = 0.0f;
    float* ob = out + ((size_t)b * C_DIM) * HW + s0 + i;
#pragma unroll 4
    for (int c2 = 0; c2 < 128; c2++) {
        int c = (c2 << 1) + cg;
        float q  = __ldg(erow + c);
        float zv = z_tile[c * TM + i];
        ob[(size_t)c * HW] = q;
        float dff = q - zv;
        lsq = fmaf(dff, dff, lsq);
        llin += dff;
    }
#pragma unroll
    for (int m = 16; m > 0; m >>= 1) {
        lsq  += __shfl_xor_sync(0xffffffffu, lsq, m);
        llin += __shfl_xor_sync(0xffffffffu, llin, m);
    }
    int wid = tid >> 5, lane = tid & 31;
    if (lane == 0) { s_red[wid] = lsq; s_red[8 + wid] = llin; }
    __syncthreads();
    if (tid == 0) {
        double a = 0.0, l = 0.0;
#pragma unroll
        for (int w = 0; w < 8; w++) { a += (double)s_red[w]; l += (double)s_red[8 + w]; }
        atomicAdd(&g_sumsq, a);
        atomicAdd(&g_sumlin, l);
    }
}

__global__ void vq_finalize_kernel(float* out, int nelem) {
    double m = (double)nelem;
    out[nelem] = (float)(g_sumsq / m + 0.25 * (g_sumlin / m));
}

// ---------------- launch ----------------
extern "C" void kernel_launch(void* const* d_in, const int* in_sizes, int n_in,
                              void* d_out, int out_size) {
    const float* z   = (const float*)d_in[0];   // [64,256,32,32]
    const float* emb = (const float*)d_in[1];   // [1024,256]
    float* out = (float*)d_out;                 // [64,256,32,32] ++ [loss]
    const int nelem = out_size - 1;             // 16777216

    const size_t smem_bytes =
        (size_t)(C_DIM * TM + CK * TN) * sizeof(float) + TM * sizeof(int) + 16 * sizeof(float);
    cudaFuncSetAttribute(vq_main_kernel,
                         cudaFuncAttributeMaxDynamicSharedMemorySize, (int)smem_bytes);

    vq_zero_kernel<<<1, 1>>>();
    vq_transpose_kernel<<<dim3(K_DIM / 32, C_DIM / 32), dim3(32, 8)>>>(emb);
    vq_esq_kernel<<<K_DIM / 256, 256>>>(emb);
    vq_zsq_kernel<<<(64 * HW) / 256, 256>>>(z);
    vq_main_kernel<<<(64 * HW) / TM, NTHREADS, smem_bytes>>>(z, emb, out);
    vq_finalize_kernel<<<1, 1>>>(out, nelem);
}

// round 5
// speedup vs baseline: 1.0932x; 1.0932x over previous
#include <cuda_runtime.h>
#include <cstdint>

#define C_DIM 256
#define K_DIM 1024
#define HW    1024
#define TM    64
#define TN    128
#define CK    64
#define NTHREADS 256

// ---------------- device globals (scratch; no runtime allocation) ----------------
__device__ __align__(16) float  g_embT[C_DIM * K_DIM];  // emb transposed: [c][k]
__device__ __align__(16) float  g_esq[K_DIM];           // ||e_k||^2 (fp32, sequential order)
__device__ __align__(16) float  g_zsq[64 * HW];         // ||z_n||^2 (fp32, sequential order)
__device__ double g_sumsq;
__device__ double g_sumlin;

// ---------------- tiny helper kernels ----------------
__global__ void vq_zero_kernel() {
    g_sumsq = 0.0;
    g_sumlin = 0.0;
}

// emb [K][C] -> g_embT [C][K], classic 32x32 smem transpose
__global__ void vq_transpose_kernel(const float* __restrict__ emb) {
    __shared__ float t[32][33];
    int k0 = blockIdx.x * 32, c0 = blockIdx.y * 32;
    int tx = threadIdx.x, ty = threadIdx.y;
#pragma unroll
    for (int r = ty; r < 32; r += 8)
        t[r][tx] = emb[(size_t)(k0 + r) * C_DIM + c0 + tx];
    __syncthreads();
#pragma unroll
    for (int r = ty; r < 32; r += 8)
        g_embT[(size_t)(c0 + r) * K_DIM + k0 + tx] = t[tx][r];
}

// ||e_k||^2: one thread per code, STRICT sequential fp32, mul/add separately rounded
__global__ void vq_esq_kernel(const float* __restrict__ emb) {
    int k = blockIdx.x * blockDim.x + threadIdx.x;
    if (k >= K_DIM) return;
    const float* row = emb + (size_t)k * C_DIM;
    float acc = 0.0f;
    for (int c = 0; c < C_DIM; c++) {
        float v = row[c];
        acc = __fadd_rn(acc, __fmul_rn(v, v));
    }
    g_esq[k] = acc;
}

// ||z_n||^2: one thread per token, STRICT sequential fp32 over c ascending
__global__ void vq_zsq_kernel(const float* __restrict__ z) {
    int n = blockIdx.x * blockDim.x + threadIdx.x;   // 0..65535
    int b = n >> 10, s = n & (HW - 1);
    const float* base = z + ((size_t)b * C_DIM) * HW + s;
    float acc = 0.0f;
    for (int c = 0; c < C_DIM; c++) {
        float v = base[(size_t)c * HW];
        acc = __fadd_rn(acc, __fmul_rn(v, v));
    }
    g_zsq[n] = acc;
}

// ---------------- packed f32x2 helpers ----------------
__device__ __forceinline__ unsigned long long splat2(float x) {
    unsigned long long r;
    unsigned int xi = __float_as_uint(x);
    asm("mov.b64 %0, {%1, %1};" : "=l"(r) : "r"(xi));
    return r;
}
__device__ __forceinline__ void fma2(unsigned long long& d,
                                     unsigned long long a,
                                     unsigned long long b) {
    asm("fma.rn.f32x2 %0, %1, %2, %0;" : "+l"(d) : "l"(a), "l"(b));
}
__device__ __forceinline__ void unpack2(unsigned long long v, float& lo, float& hi) {
    unsigned int l, h;
    asm("mov.b64 {%0, %1}, %2;" : "=r"(l), "=r"(h) : "l"(v));
    lo = __uint_as_float(l);
    hi = __uint_as_float(h);
}

// Emulate reference fp32 chain: d = fl( fl(zsq + esq) - fl(2*ez) )
__device__ __forceinline__ float ref_dist(float zsq, float esq, float ez) {
    float t = __fadd_rn(zsq, esq);
    return __fadd_rn(t, __fmul_rn(-2.0f, ez));
}

// ---------------- main kernel: distances + argmin + gather + loss ----------------
// TM=64 -> 96.3KB smem/CTA -> 2 CTAs/SM resident (4 warps/SMSP): stage loads &
// syncs of one CTA hide under the other CTA's FMA stream; CTA granularity halves
// so per-SM work imbalance drops from ~15.6% to ~1.2%.
__global__ __launch_bounds__(NTHREADS, 2)
void vq_main_kernel(const float* __restrict__ z, const float* __restrict__ emb,
                    float* __restrict__ out) {
    extern __shared__ float smem[];
    float* z_tile = smem;                       // [256][64]   (c-major, token contiguous)
    float* e_tile = smem + C_DIM * TM;          // [64][128]   (c-major, code contiguous)
    int*   s_inds = (int*)(e_tile + CK * TN);   // [64]
    float* s_red  = (float*)(s_inds + TM);      // [16]

    const int tid = threadIdx.x;
    const int tx = tid & 15;   // code group (8 codes: tx*4..+3 and 64+tx*4..+3)
    const int ty = tid >> 4;   // token group (4 tokens: ty*4..+3)
    const int blk = blockIdx.x;
    const int b  = blk >> 4;               // 16 blocks per image (1024/64)
    const int s0 = (blk & 15) * TM;
    const float* zb = z + ((size_t)b * C_DIM) * HW + s0;

    // load z tile: z_tile[c][i] = z[b][c][s0+i]  (fully coalesced)
#pragma unroll
    for (int r = 0; r < 16; r++) {
        int idx = tid + r * NTHREADS;          // 0..4095 float4s
        int c = idx >> 4, i4 = idx & 15;
        *(float4*)&z_tile[c * TM + i4 * 4] =
            *(const float4*)(zb + (size_t)c * HW + i4 * 4);
    }

    // per-token ||z||^2 (reference fp32 bits) for the 4 tokens this thread owns
    float zs4[4];
#pragma unroll
    for (int t = 0; t < 4; t++)
        zs4[t] = g_zsq[b * HW + s0 + (ty << 2) + t];

    float bmin[4];
    int   bidx[4];
#pragma unroll
    for (int t = 0; t < 4; t++) { bmin[t] = 3.4e38f; bidx[t] = 0; }

    for (int kc = 0; kc < 8; kc++) {           // 8 code chunks of 128
        unsigned long long acc[4][4];
#pragma unroll
        for (int t = 0; t < 4; t++)
#pragma unroll
            for (int p = 0; p < 4; p++) acc[t][p] = 0ull;

        for (int cc = 0; cc < 4; cc++) {       // C staged in 4 chunks of 64, c ASCENDING
            __syncthreads();
            {   // stage embT[cc*64 .. +64][kc*128 .. +128] into smem
                const float* src = g_embT + (size_t)(cc * CK) * K_DIM + kc * TN;
#pragma unroll
                for (int r = 0; r < 8; r++) {
                    int idx = tid + r * NTHREADS;  // 0..2047 float4s
                    int c = idx >> 5, k4 = idx & 31;
                    *(float4*)&e_tile[c * TN + k4 * 4] =
                        *(const float4*)(src + (size_t)c * K_DIM + k4 * 4);
                }
            }
            __syncthreads();

            const float* zr = z_tile + (cc * CK) * TM + (ty << 2);
            const float* er = e_tile + (tx << 2);
#pragma unroll 8
            for (int cl = 0; cl < CK; cl++) {
                float4 zz = *(const float4*)(zr);
                ulonglong2 eA = *(const ulonglong2*)(er);        // codes tx*4 .. +3
                ulonglong2 eB = *(const ulonglong2*)(er + 64);   // codes 64+tx*4 .. +3
                float zv[4] = {zz.x, zz.y, zz.z, zz.w};
                unsigned long long e0 = eA.x, e1 = eA.y, e2 = eB.x, e3 = eB.y;
#pragma unroll
                for (int t = 0; t < 4; t++) {
                    unsigned long long zs = splat2(zv[t]);
                    fma2(acc[t][0], zs, e0);   // sequential fused-FMA over c, per code
                    fma2(acc[t][1], zs, e1);
                    fma2(acc[t][2], zs, e2);
                    fma2(acc[t][3], zs, e3);
                }
                zr += TM;
                er += TN;
            }
        }

        // epilogue: reference-emulated dist = fl(fl(zsq+esq) - fl(2*ez))
        const int kA = kc * TN + (tx << 2);
        const int kB = kA + 64;
        float4 eqA = *(const float4*)&g_esq[kA];
        float4 eqB = *(const float4*)&g_esq[kB];
#pragma unroll
        for (int t = 0; t < 4; t++) {
            const float zs = zs4[t];
            float lo, hi;
            unpack2(acc[t][0], lo, hi);
            float da0 = ref_dist(zs, eqA.x, lo);
            float da1 = ref_dist(zs, eqA.y, hi);
            unpack2(acc[t][1], lo, hi);
            float da2 = ref_dist(zs, eqA.z, lo);
            float da3 = ref_dist(zs, eqA.w, hi);
            unpack2(acc[t][2], lo, hi);
            float db0 = ref_dist(zs, eqB.x, lo);
            float db1 = ref_dist(zs, eqB.y, hi);
            unpack2(acc[t][3], lo, hi);
            float db2 = ref_dist(zs, eqB.z, lo);
            float db3 = ref_dist(zs, eqB.w, hi);

            float bd = da0; int bk = kA;                    // ascending k, strict <
            if (da1 < bd) { bd = da1; bk = kA + 1; }
            if (da2 < bd) { bd = da2; bk = kA + 2; }
            if (da3 < bd) { bd = da3; bk = kA + 3; }
            if (db0 < bd) { bd = db0; bk = kB;     }
            if (db1 < bd) { bd = db1; bk = kB + 1; }
            if (db2 < bd) { bd = db2; bk = kB + 2; }
            if (db3 < bd) { bd = db3; bk = kB + 3; }
#pragma unroll
            for (int m = 8; m > 0; m >>= 1) {               // reduce over 16 tx lanes
                float od = __shfl_xor_sync(0xffffffffu, bd, m);
                int   ok = __shfl_xor_sync(0xffffffffu, bk, m);
                if (od < bd || (od == bd && ok < bk)) { bd = od; bk = ok; }
            }
            if (bd < bmin[t]) { bmin[t] = bd; bidx[t] = bk; }  // earlier chunk wins ties
        }
    }

    if (tx == 0) {
#pragma unroll
        for (int t = 0; t < 4; t++) s_inds[(ty << 2) + t] = bidx[t];
    }
    __syncthreads();

    // gather z_q = emb[ind], write NCHW (coalesced), accumulate loss terms
    const int i  = tid & 63;
    const int cg = tid >> 6;                    // 0..3: c residue class
    const int ind = s_inds[i];
    const float* erow = emb + (size_t)ind * C_DIM;
    float lsq = 0.0f, llin = 0.0f;
    float* ob = out + ((size_t)b * C_DIM) * HW + s0 + i;
#pragma unroll 4
    for (int c2 = 0; c2 < 64; c2++) {
        int c = (c2 << 2) + cg;
        float q  = __ldg(erow + c);
        float zv = z_tile[c * TM + i];
        ob[(size_t)c * HW] = q;
        float dff = q - zv;
        lsq = fmaf(dff, dff, lsq);
        llin += dff;
    }
#pragma unroll
    for (int m = 16; m > 0; m >>= 1) {
        lsq  += __shfl_xor_sync(0xffffffffu, lsq, m);
        llin += __shfl_xor_sync(0xffffffffu, llin, m);
    }
    int wid = tid >> 5, lane = tid & 31;
    if (lane == 0) { s_red[wid] = lsq; s_red[8 + wid] = llin; }
    __syncthreads();
    if (tid == 0) {
        double a = 0.0, l = 0.0;
#pragma unroll
        for (int w = 0; w < 8; w++) { a += (double)s_red[w]; l += (double)s_red[8 + w]; }
        atomicAdd(&g_sumsq, a);
        atomicAdd(&g_sumlin, l);
    }
}

__global__ void vq_finalize_kernel(float* out, int nelem) {
    double m = (double)nelem;
    out[nelem] = (float)(g_sumsq / m + 0.25 * (g_sumlin / m));
}

// ---------------- launch ----------------
extern "C" void kernel_launch(void* const* d_in, const int* in_sizes, int n_in,
                              void* d_out, int out_size) {
    const float* z   = (const float*)d_in[0];   // [64,256,32,32]
    const float* emb = (const float*)d_in[1];   // [1024,256]
    float* out = (float*)d_out;                 // [64,256,32,32] ++ [loss]
    const int nelem = out_size - 1;             // 16777216

    const size_t smem_bytes =
        (size_t)(C_DIM * TM + CK * TN) * sizeof(float) + TM * sizeof(int) + 16 * sizeof(float);
    cudaFuncSetAttribute(vq_main_kernel,
                         cudaFuncAttributeMaxDynamicSharedMemorySize, (int)smem_bytes);

    vq_zero_kernel<<<1, 1>>>();
    vq_transpose_kernel<<<dim3(K_DIM / 32, C_DIM / 32), dim3(32, 8)>>>(emb);
    vq_esq_kernel<<<K_DIM / 256, 256>>>(emb);
    vq_zsq_kernel<<<(64 * HW) / 256, 256>>>(z);
    vq_main_kernel<<<(64 * HW) / TM, NTHREADS, smem_bytes>>>(z, emb, out);
    vq_finalize_kernel<<<1, 1>>>(out, nelem);
}